// round 15
// baseline (speedup 1.0000x reference)
#include <cuda_runtime.h>

#define IMG_H 4200
#define IMG_W 3200
#define HF 84
#define WF 64
#define NB 8
#define ROW_F2 (IMG_W / 2)           // 1600 float2 per image row
#define FEAT (NB * 2 * HF * WF)      // 86016
#define N_ROWS (NB * HF)             // 672 feature rows

// conv1 partial sums per 10-row chunk: [chunk][n][ch][ty][tx]  (1.72 MB)
// 16B-aligned so the head can read it with LDG.128.
__device__ __align__(16) float g_part[5][FEAT];
// dynamic work queue; zero-init at load, reset by head_kernel each launch.
__device__ unsigned g_tickets[5];

#define FMA_F32X2(acc, a, b) \
    asm("fma.rn.f32x2 %0, %1, %2, %0;" : "+l"(acc) : "l"(a), "l"(b))
#define UNPACK_F32X2(lo, hi, in) \
    asm("mov.b64 {%0, %1}, %2;" : "=f"(lo), "=f"(hi) : "l"(in))

// ---------------------------------------------------------------------------
// Kernel 1: 50x50 stride-50 VALID conv, 1->2 ch (non-overlapping patches).
// R9 layout (best measured): item = (chunk, feature row) = 10 consecutive
// image rows (128 KB contiguous); thread t<400 owns f2-cols
// {t,t+400,t+800,t+1200}; dynamic per-chunk tickets with prefetch
// (295 blocks = single wave); ONE double-buffered barrier per item.
// NEW: packed fma.rn.f32x2 — the LDG.64 value is used directly as an f32x2;
// accumulators stay lane-split (x-partial, y-partial) and combine once per
// item. 80 FFMA2 per item instead of 160 FFMA; zero packing instructions.
// ---------------------------------------------------------------------------
__global__ __launch_bounds__(416, 2) void conv1_kernel(const float* __restrict__ X,
                                                       const float* __restrict__ w)
{
    __shared__ float    s_part[2][2][1600];   // [buf][ch][f2col]  25.6 KB
    __shared__ unsigned s_ri[2];

    const int t = threadIdx.x;
    const bool active = (t < 400);
    const int chunk = blockIdx.x % 5;         // tile rows chunk*10 .. +9

    // packed register weights: rows chunk*10+r, f2-col t%25, per channel
    const unsigned long long* wp0 = (const unsigned long long*)w;          // ch0
    const unsigned long long* wp1 = (const unsigned long long*)(w + 2500); // ch1
    const int wc = active ? (t % 25) : 0;
    unsigned long long w0p[10], w1p[10];
#pragma unroll
    for (int r = 0; r < 10; r++) {
        const int wi = (chunk * 10 + r) * 25 + wc;
        w0p[r] = active ? wp0[wi] : 0ull;
        w1p[r] = active ? wp1[wi] : 0ull;
    }

    if (t == 0) s_ri[0] = atomicAdd(&g_tickets[chunk], 1u);
    __syncthreads();

#pragma unroll 1
    for (int j = 0; ; j++) {
        const int buf = j & 1;
        const unsigned ri = s_ri[buf];        // uniform across block
        if (ri >= N_ROWS) break;

        if (t == 0) s_ri[buf ^ 1] = atomicAdd(&g_tickets[chunk], 1u);  // prefetch

        const int n  = ri / HF;
        const int ty = ri % HF;

        if (active) {
            const unsigned long long* base = (const unsigned long long*)
                ((const float2*)X
                 + (size_t)n * (IMG_H * ROW_F2)
                 + (size_t)(ty * 50 + chunk * 10) * ROW_F2
                 + t);

            // acc[k*2+ch] packed: (sum of x-lane terms, sum of y-lane terms)
            unsigned long long acc[8];
#pragma unroll
            for (int i = 0; i < 8; i++) acc[i] = 0ull;

#pragma unroll
            for (int r = 0; r < 10; r++) {
#pragma unroll
                for (int k = 0; k < 4; k++) {
                    const unsigned long long xv = __ldg(base + r * ROW_F2 + k * 400);
                    FMA_F32X2(acc[k * 2 + 0], xv, w0p[r]);
                    FMA_F32X2(acc[k * 2 + 1], xv, w1p[r]);
                }
            }
#pragma unroll
            for (int k = 0; k < 4; k++) {
                float lo0, hi0, lo1, hi1;
                UNPACK_F32X2(lo0, hi0, acc[k * 2 + 0]);
                UNPACK_F32X2(lo1, hi1, acc[k * 2 + 1]);
                s_part[buf][0][t + k * 400] = lo0 + hi0;
                s_part[buf][1][t + k * 400] = lo1 + hi1;
            }
        }
        __syncthreads();   // s_part[buf] + next ticket ready; prev buf free

        // 128 finalizers: ch = t>>6, tile = t&63 (stride-25 smem reads are
        // bank-clean; 64-float coalesced g_part stores)
        if (t < 128) {
            const int ch = t >> 6, tile = t & 63;
            float s = 0.f;
#pragma unroll
            for (int m = 0; m < 25; m++) s += s_part[buf][ch][tile * 25 + m];
            g_part[chunk][((n * 2 + ch) * HF + ty) * WF + tile] = s;
        }
    }
    cudaTriggerProgrammaticLaunchCompletion();
}

// ---------------------------------------------------------------------------
// Kernel 2: fused head (best shape: 336 blocks x 128 threads, 2 feature
// rows/block). PDL: weight prologue overlaps conv1 drain; gridsync before
// g_part. NEW: staging reads g_part as float4 — 5 LDG.128 per thread
// (was 20 scalar LDG) -> 4x the memory-level parallelism at low occupancy.
// ---------------------------------------------------------------------------
__global__ __launch_bounds__(128) void head_kernel(const float* __restrict__ conv_b,
                                                   const float* __restrict__ box_w,
                                                   const float* __restrict__ box_b,
                                                   const float* __restrict__ cls_w,
                                                   const float* __restrict__ cls_b,
                                                   float4* __restrict__ out)
{
    __shared__ float  s_bw[36 * 18];       // box_w [36,2,3,3]
    __shared__ float  s_bb[36];
    __shared__ float  s_cw[36];            // cls_w [2,2,3,3]
    __shared__ float  s_cb[2];
    __shared__ __align__(16) float s_f[2][4][64];  // feats ch x rows x cols
    __shared__ float4 s_stage[128 * 9];    // output staging (18 KB)

    const int tid = threadIdx.x;

    // ---- prologue (overlaps conv1 drain under PDL) ----
    for (int i = tid; i < 36 * 18; i += 128) s_bw[i] = box_w[i];
    if (tid < 36) {
        s_bb[tid] = box_b[tid];
        s_cw[tid] = cls_w[tid];
    }
    if (tid < 2) s_cb[tid] = cls_b[tid];

    const int n  = blockIdx.x / 42;
    const int y0 = (blockIdx.x % 42) * 2;   // block covers rows y0, y0+1
    const float cb0 = conv_b[0], cb1 = conv_b[1];

    cudaGridDependencySynchronize();        // conv1's g_part now visible

    // reset work-queue tickets for the next launch (conv1 provably done)
    if (blockIdx.x == 0 && tid < 5) g_tickets[tid] = 0;

    // stage feats rows y0-1..y0+2: one float4 per thread, summing 5 chunk
    // partials + bias. tid -> (ic = tid>>6, rr = (tid>>4)&3, xq = tid&15)
    {
        const int ic = tid >> 6;
        const int rr = (tid >> 4) & 3;
        const int xq = tid & 15;            // f4-column within the 64-row
        const int yy = y0 - 1 + rr;
        const float cb = ic ? cb1 : cb0;
        float4 v = make_float4(0.f, 0.f, 0.f, 0.f);
        if (yy >= 0 && yy < HF) {
            const int idx4 = (((n * 2 + ic) * HF + yy) * WF) / 4 + xq;
            v = make_float4(cb, cb, cb, cb);
#pragma unroll
            for (int c = 0; c < 5; c++) {
                const float4 p = __ldg((const float4*)g_part[c] + idx4);
                v.x += p.x; v.y += p.y; v.z += p.z; v.w += p.w;
            }
        }
        ((float4*)s_f)[tid] = v;            // flat f4 index == tid by layout
    }
    __syncthreads();

    const int x  = tid & 63;
    const int ly = tid >> 6;                // 0 or 1
    const int y  = y0 + ly;

    // gather 3x3x2 neighborhood from smem (x edges zero-padded)
    float f[18];
#pragma unroll
    for (int ic = 0; ic < 2; ic++) {
#pragma unroll
        for (int dy = 0; dy < 3; dy++) {
#pragma unroll
            for (int dx = 0; dx < 3; dx++) {
                const int xx = x + dx - 1;
                float v = 0.0f;
                if (xx >= 0 && xx < WF) v = s_f[ic][ly + dy][xx];
                f[ic * 9 + dy * 3 + dx] = v;
            }
        }
    }

    // cls conv + 2-channel softmax threshold
    float c0 = s_cb[0], c1 = s_cb[1];
#pragma unroll
    for (int k = 0; k < 18; k++) {
        c0 += f[k] * s_cw[k];
        c1 += f[k] * s_cw[18 + k];
    }
    const float m  = fmaxf(c0, c1);
    const float e0 = __expf(c0 - m), e1 = __expf(c1 - m);
    const float p1 = e1 / (e0 + e1);
    const float mval = (p1 > 0.95f) ? 1.0f : 0.0f;

    const float gx = ((float)x + 0.5f) * 50.0f;
    const float gy = ((float)y + 0.5f) * 50.0f;
    const float SZ[3] = {16.0f, 32.0f, 64.0f};
    const float RI[3] = {0.70710678118654752f, 1.0f, 1.41421356237309505f};

#pragma unroll
    for (int a = 0; a < 9; a++) {
        float o0 = s_bb[a * 4 + 0], o1 = s_bb[a * 4 + 1];
        float o2 = s_bb[a * 4 + 2], o3 = s_bb[a * 4 + 3];
        const float* wp = &s_bw[a * 4 * 18];
#pragma unroll
        for (int kk = 0; kk < 18; kk++) {
            const float fv = f[kk];
            o0 += fv * wp[kk];
            o1 += fv * wp[18 + kk];
            o2 += fv * wp[36 + kk];
            o3 += fv * wp[54 + kk];
        }
        const float s  = SZ[a / 3];
        const float r  = RI[a % 3];
        const float wa = (s / r) * 0.5f;
        const float ha = (s * r) * 0.5f;
        float v0 = fminf(fmaxf(gx - wa + o0, 0.0f), (float)IMG_W);
        float v1 = fminf(fmaxf(gy - ha + o1, 0.0f), (float)IMG_H);
        float v2 = fminf(fmaxf(gx + wa + o2, 0.0f), (float)IMG_W);
        float v3 = fminf(fmaxf(gy + ha + o3, 0.0f), (float)IMG_H);
        s_stage[tid * 9 + a] =
            make_float4(v0 * mval, v1 * mval, v2 * mval, v3 * mval);
    }
    __syncthreads();

    // coalesced copy-out: block's 128 positions = 1152 contiguous float4
    float4* bout = out + (size_t)blockIdx.x * 128 * 9;
#pragma unroll
    for (int i = 0; i < 9; i++)
        bout[tid + 128 * i] = s_stage[tid + 128 * i];
}

extern "C" void kernel_launch(void* const* d_in, const int* in_sizes, int n_in,
                              void* d_out, int out_size)
{
    const float* X      = (const float*)d_in[0];
    const float* conv_w = (const float*)d_in[1];
    const float* conv_b = (const float*)d_in[2];
    const float* box_w  = (const float*)d_in[3];
    const float* box_b  = (const float*)d_in[4];
    const float* cls_w  = (const float*)d_in[5];
    const float* cls_b  = (const float*)d_in[6];
    float4* out = (float4*)d_out;

    // 295 blocks (59 per chunk) -- single wave, dynamic tickets
    conv1_kernel<<<295, 416>>>(X, conv_w);

    // head with programmatic dependent launch (prologue overlaps conv1 drain)
    cudaLaunchConfig_t cfg = {};
    cfg.gridDim  = dim3(336, 1, 1);
    cfg.blockDim = dim3(128, 1, 1);
    cfg.dynamicSmemBytes = 0;
    cfg.stream = 0;
    cudaLaunchAttribute attrs[1];
    attrs[0].id = cudaLaunchAttributeProgrammaticStreamSerialization;
    attrs[0].val.programmaticStreamSerializationAllowed = 1;
    cfg.attrs = attrs;
    cfg.numAttrs = 1;
    cudaLaunchKernelEx(&cfg, head_kernel, conv_b, box_w, box_b, cls_w, cls_b, out);
}

// round 16
// speedup vs baseline: 1.0132x; 1.0132x over previous
#include <cuda_runtime.h>

#define IMG_H 4200
#define IMG_W 3200
#define HF 84
#define WF 64
#define NB 8
#define ROW_F2 (IMG_W / 2)           // 1600 float2 per image row
#define FEAT (NB * 2 * HF * WF)      // 86016
#define N_ROWS (NB * HF)             // 672 feature rows

// conv1 partial sums per 10-row chunk: [chunk][n][ch][ty][tx]  (1.72 MB)
// 16B-aligned so the head can read it with LDG.128.
__device__ __align__(16) float g_part[5][FEAT];
// dynamic work queue; zero-init at load, reset by head_kernel each launch.
__device__ unsigned g_tickets[5];

#define FMA_F32X2(acc, a, b) \
    asm("fma.rn.f32x2 %0, %1, %2, %0;" : "+l"(acc) : "l"(a), "l"(b))
#define UNPACK_F32X2(lo, hi, in) \
    asm("mov.b64 {%0, %1}, %2;" : "=f"(lo), "=f"(hi) : "l"(in))

// ---------------------------------------------------------------------------
// Kernel 1: 50x50 stride-50 VALID conv, 1->2 ch (non-overlapping patches).
// R9 layout (best measured): item = (chunk, feature row) = 10 consecutive
// image rows (128 KB contiguous); thread t<400 owns f2-cols
// {t,t+400,t+800,t+1200}; dynamic per-chunk tickets with prefetch
// (295 blocks = single wave); ONE double-buffered barrier per item.
// NEW: packed fma.rn.f32x2 — the LDG.64 value is used directly as an f32x2;
// accumulators stay lane-split (x-partial, y-partial) and combine once per
// item. 80 FFMA2 per item instead of 160 FFMA; zero packing instructions.
// ---------------------------------------------------------------------------
__global__ __launch_bounds__(416, 2) void conv1_kernel(const float* __restrict__ X,
                                                       const float* __restrict__ w)
{
    __shared__ float    s_part[2][2][1600];   // [buf][ch][f2col]  25.6 KB
    __shared__ unsigned s_ri[2];

    const int t = threadIdx.x;
    const bool active = (t < 400);
    const int chunk = blockIdx.x % 5;         // tile rows chunk*10 .. +9

    // packed register weights: rows chunk*10+r, f2-col t%25, per channel
    const unsigned long long* wp0 = (const unsigned long long*)w;          // ch0
    const unsigned long long* wp1 = (const unsigned long long*)(w + 2500); // ch1
    const int wc = active ? (t % 25) : 0;
    unsigned long long w0p[10], w1p[10];
#pragma unroll
    for (int r = 0; r < 10; r++) {
        const int wi = (chunk * 10 + r) * 25 + wc;
        w0p[r] = active ? wp0[wi] : 0ull;
        w1p[r] = active ? wp1[wi] : 0ull;
    }

    if (t == 0) s_ri[0] = atomicAdd(&g_tickets[chunk], 1u);
    __syncthreads();

#pragma unroll 1
    for (int j = 0; ; j++) {
        const int buf = j & 1;
        const unsigned ri = s_ri[buf];        // uniform across block
        if (ri >= N_ROWS) break;

        if (t == 0) s_ri[buf ^ 1] = atomicAdd(&g_tickets[chunk], 1u);  // prefetch

        const int n  = ri / HF;
        const int ty = ri % HF;

        if (active) {
            const unsigned long long* base = (const unsigned long long*)
                ((const float2*)X
                 + (size_t)n * (IMG_H * ROW_F2)
                 + (size_t)(ty * 50 + chunk * 10) * ROW_F2
                 + t);

            // acc[k*2+ch] packed: (sum of x-lane terms, sum of y-lane terms)
            unsigned long long acc[8];
#pragma unroll
            for (int i = 0; i < 8; i++) acc[i] = 0ull;

#pragma unroll
            for (int r = 0; r < 10; r++) {
#pragma unroll
                for (int k = 0; k < 4; k++) {
                    const unsigned long long xv = __ldg(base + r * ROW_F2 + k * 400);
                    FMA_F32X2(acc[k * 2 + 0], xv, w0p[r]);
                    FMA_F32X2(acc[k * 2 + 1], xv, w1p[r]);
                }
            }
#pragma unroll
            for (int k = 0; k < 4; k++) {
                float lo0, hi0, lo1, hi1;
                UNPACK_F32X2(lo0, hi0, acc[k * 2 + 0]);
                UNPACK_F32X2(lo1, hi1, acc[k * 2 + 1]);
                s_part[buf][0][t + k * 400] = lo0 + hi0;
                s_part[buf][1][t + k * 400] = lo1 + hi1;
            }
        }
        __syncthreads();   // s_part[buf] + next ticket ready; prev buf free

        // 128 finalizers: ch = t>>6, tile = t&63 (stride-25 smem reads are
        // bank-clean; 64-float coalesced g_part stores)
        if (t < 128) {
            const int ch = t >> 6, tile = t & 63;
            float s = 0.f;
#pragma unroll
            for (int m = 0; m < 25; m++) s += s_part[buf][ch][tile * 25 + m];
            g_part[chunk][((n * 2 + ch) * HF + ty) * WF + tile] = s;
        }
    }
    cudaTriggerProgrammaticLaunchCompletion();
}

// ---------------------------------------------------------------------------
// Kernel 2: fused head (best shape: 336 blocks x 128 threads, 2 feature
// rows/block). PDL: weight prologue overlaps conv1 drain; gridsync before
// g_part. NEW: staging reads g_part as float4 — 5 LDG.128 per thread
// (was 20 scalar LDG) -> 4x the memory-level parallelism at low occupancy.
// ---------------------------------------------------------------------------
__global__ __launch_bounds__(128) void head_kernel(const float* __restrict__ conv_b,
                                                   const float* __restrict__ box_w,
                                                   const float* __restrict__ box_b,
                                                   const float* __restrict__ cls_w,
                                                   const float* __restrict__ cls_b,
                                                   float4* __restrict__ out)
{
    __shared__ float  s_bw[36 * 18];       // box_w [36,2,3,3]
    __shared__ float  s_bb[36];
    __shared__ float  s_cw[36];            // cls_w [2,2,3,3]
    __shared__ float  s_cb[2];
    __shared__ __align__(16) float s_f[2][4][64];  // feats ch x rows x cols
    __shared__ float4 s_stage[128 * 9];    // output staging (18 KB)

    const int tid = threadIdx.x;

    // ---- prologue (overlaps conv1 drain under PDL) ----
    for (int i = tid; i < 36 * 18; i += 128) s_bw[i] = box_w[i];
    if (tid < 36) {
        s_bb[tid] = box_b[tid];
        s_cw[tid] = cls_w[tid];
    }
    if (tid < 2) s_cb[tid] = cls_b[tid];

    const int n  = blockIdx.x / 42;
    const int y0 = (blockIdx.x % 42) * 2;   // block covers rows y0, y0+1
    const float cb0 = conv_b[0], cb1 = conv_b[1];

    cudaGridDependencySynchronize();        // conv1's g_part now visible

    // reset work-queue tickets for the next launch (conv1 provably done)
    if (blockIdx.x == 0 && tid < 5) g_tickets[tid] = 0;

    // stage feats rows y0-1..y0+2: one float4 per thread, summing 5 chunk
    // partials + bias. tid -> (ic = tid>>6, rr = (tid>>4)&3, xq = tid&15)
    {
        const int ic = tid >> 6;
        const int rr = (tid >> 4) & 3;
        const int xq = tid & 15;            // f4-column within the 64-row
        const int yy = y0 - 1 + rr;
        const float cb = ic ? cb1 : cb0;
        float4 v = make_float4(0.f, 0.f, 0.f, 0.f);
        if (yy >= 0 && yy < HF) {
            const int idx4 = (((n * 2 + ic) * HF + yy) * WF) / 4 + xq;
            v = make_float4(cb, cb, cb, cb);
#pragma unroll
            for (int c = 0; c < 5; c++) {
                const float4 p = __ldg((const float4*)g_part[c] + idx4);
                v.x += p.x; v.y += p.y; v.z += p.z; v.w += p.w;
            }
        }
        ((float4*)s_f)[tid] = v;            // flat f4 index == tid by layout
    }
    __syncthreads();

    const int x  = tid & 63;
    const int ly = tid >> 6;                // 0 or 1
    const int y  = y0 + ly;

    // gather 3x3x2 neighborhood from smem (x edges zero-padded)
    float f[18];
#pragma unroll
    for (int ic = 0; ic < 2; ic++) {
#pragma unroll
        for (int dy = 0; dy < 3; dy++) {
#pragma unroll
            for (int dx = 0; dx < 3; dx++) {
                const int xx = x + dx - 1;
                float v = 0.0f;
                if (xx >= 0 && xx < WF) v = s_f[ic][ly + dy][xx];
                f[ic * 9 + dy * 3 + dx] = v;
            }
        }
    }

    // cls conv + 2-channel softmax threshold
    float c0 = s_cb[0], c1 = s_cb[1];
#pragma unroll
    for (int k = 0; k < 18; k++) {
        c0 += f[k] * s_cw[k];
        c1 += f[k] * s_cw[18 + k];
    }
    const float m  = fmaxf(c0, c1);
    const float e0 = __expf(c0 - m), e1 = __expf(c1 - m);
    const float p1 = e1 / (e0 + e1);
    const float mval = (p1 > 0.95f) ? 1.0f : 0.0f;

    const float gx = ((float)x + 0.5f) * 50.0f;
    const float gy = ((float)y + 0.5f) * 50.0f;
    const float SZ[3] = {16.0f, 32.0f, 64.0f};
    const float RI[3] = {0.70710678118654752f, 1.0f, 1.41421356237309505f};

#pragma unroll
    for (int a = 0; a < 9; a++) {
        float o0 = s_bb[a * 4 + 0], o1 = s_bb[a * 4 + 1];
        float o2 = s_bb[a * 4 + 2], o3 = s_bb[a * 4 + 3];
        const float* wp = &s_bw[a * 4 * 18];
#pragma unroll
        for (int kk = 0; kk < 18; kk++) {
            const float fv = f[kk];
            o0 += fv * wp[kk];
            o1 += fv * wp[18 + kk];
            o2 += fv * wp[36 + kk];
            o3 += fv * wp[54 + kk];
        }
        const float s  = SZ[a / 3];
        const float r  = RI[a % 3];
        const float wa = (s / r) * 0.5f;
        const float ha = (s * r) * 0.5f;
        float v0 = fminf(fmaxf(gx - wa + o0, 0.0f), (float)IMG_W);
        float v1 = fminf(fmaxf(gy - ha + o1, 0.0f), (float)IMG_H);
        float v2 = fminf(fmaxf(gx + wa + o2, 0.0f), (float)IMG_W);
        float v3 = fminf(fmaxf(gy + ha + o3, 0.0f), (float)IMG_H);
        s_stage[tid * 9 + a] =
            make_float4(v0 * mval, v1 * mval, v2 * mval, v3 * mval);
    }
    __syncthreads();

    // coalesced copy-out: block's 128 positions = 1152 contiguous float4
    float4* bout = out + (size_t)blockIdx.x * 128 * 9;
#pragma unroll
    for (int i = 0; i < 9; i++)
        bout[tid + 128 * i] = s_stage[tid + 128 * i];
}

extern "C" void kernel_launch(void* const* d_in, const int* in_sizes, int n_in,
                              void* d_out, int out_size)
{
    const float* X      = (const float*)d_in[0];
    const float* conv_w = (const float*)d_in[1];
    const float* conv_b = (const float*)d_in[2];
    const float* box_w  = (const float*)d_in[3];
    const float* box_b  = (const float*)d_in[4];
    const float* cls_w  = (const float*)d_in[5];
    const float* cls_b  = (const float*)d_in[6];
    float4* out = (float4*)d_out;

    // 295 blocks (59 per chunk) -- single wave, dynamic tickets
    conv1_kernel<<<295, 416>>>(X, conv_w);

    // head with programmatic dependent launch (prologue overlaps conv1 drain)
    cudaLaunchConfig_t cfg = {};
    cfg.gridDim  = dim3(336, 1, 1);
    cfg.blockDim = dim3(128, 1, 1);
    cfg.dynamicSmemBytes = 0;
    cfg.stream = 0;
    cudaLaunchAttribute attrs[1];
    attrs[0].id = cudaLaunchAttributeProgrammaticStreamSerialization;
    attrs[0].val.programmaticStreamSerializationAllowed = 1;
    cfg.attrs = attrs;
    cfg.numAttrs = 1;
    cudaLaunchKernelEx(&cfg, head_kernel, conv_b, box_w, box_b, cls_w, cls_b, out);
}

// round 17
// speedup vs baseline: 1.1724x; 1.1571x over previous
#include <cuda_runtime.h>

#define IMG_H 4200
#define IMG_W 3200
#define HF 84
#define WF 64
#define NB 8
#define ROW_F2 (IMG_W / 2)           // 1600 float2 per image row
#define FEAT (NB * 2 * HF * WF)      // 86016
#define N_ROWS (NB * HF)             // 672 feature rows
#define NBLK 295                     // single wave: 295 < 148*2

// conv1 partial sums per 10-row chunk: [chunk][n][ch][ty][tx]  (1.72 MB)
__device__ float g_part[5][FEAT];
// work queue + barrier counters; zero-init at load, reset by elected last
// block each launch -> invariant "all zero on entry" holds every replay.
__device__ unsigned g_tickets[5];
__device__ unsigned g_done;
__device__ unsigned g_done2;

// ---------------------------------------------------------------------------
// ONE fused persistent kernel (single graph node).
// Phase 1 (conv1): exact best-measured R9 config -- item = (chunk, feature
// row) = 10 consecutive image rows (128 KB contiguous); thread t<400 owns
// f2-cols {t,t+400,t+800,t+1200} with 10 float4 register weights; dynamic
// per-chunk tickets with prefetch; ONE double-buffered barrier per item.
// Grid barrier: one fence/thread + one atomic/block, spin (nanosleep) only
// in the tail. 295 blocks = all resident (2/SM) -> cannot deadlock.
// Phase 2 (head): blocks 0..111 each process 3 two-row units with 384
// threads (weights pre-staged in smem BEFORE the spin). Direct dense
// float4 stores. Total: no second launch ramp, no PDL handoff.
// ---------------------------------------------------------------------------
__global__ __launch_bounds__(416, 2) void rpn_fused_kernel(
    const float* __restrict__ X,
    const float* __restrict__ w,
    const float* __restrict__ conv_b,
    const float* __restrict__ box_w,
    const float* __restrict__ box_b,
    const float* __restrict__ cls_w,
    const float* __restrict__ cls_b,
    float4* __restrict__ out)
{
    __shared__ float    s_part[2][2][1600];   // [buf][ch][f2col]  25.6 KB
    __shared__ unsigned s_ri[2];
    __shared__ float    s_bw[36 * 18];        // box_w   2.6 KB
    __shared__ float    s_bb[36];
    __shared__ float    s_cw[36];
    __shared__ float    s_cb[2];
    __shared__ float    s_cbias[2];
    __shared__ float    s_f[3][2][4][64];     // [sub][ch][row][col]  6 KB

    const int t = threadIdx.x;
    const bool active = (t < 400);
    const int chunk = blockIdx.x % 5;         // tile rows chunk*10 .. +9

    // ---- head weights -> smem NOW (hidden under conv1 compute) ----
    for (int i = t; i < 36 * 18; i += 416) s_bw[i] = box_w[i];
    if (t < 36) {
        s_bb[t] = box_b[t];
        s_cw[t] = cls_w[t];
    }
    if (t < 2) {
        s_cb[t]    = cls_b[t];
        s_cbias[t] = conv_b[t];
    }

    // ---- conv1 register weights: rows chunk*10+r, f2-col t%25 ----
    const float2* wv0 = (const float2*)w;           // ch0: 1250 f2
    const float2* wv1 = (const float2*)(w + 2500);  // ch1
    const int wc = active ? (t % 25) : 0;
    float4 wr[10];
#pragma unroll
    for (int r = 0; r < 10; r++) {
        const int wi = (chunk * 10 + r) * 25 + wc;
        const float2 p0 = active ? wv0[wi] : make_float2(0.f, 0.f);
        const float2 p1 = active ? wv1[wi] : make_float2(0.f, 0.f);
        wr[r] = make_float4(p0.x, p0.y, p1.x, p1.y);
    }

    if (t == 0) s_ri[0] = atomicAdd(&g_tickets[chunk], 1u);
    __syncthreads();

    // ================= Phase 1: conv1 =================
#pragma unroll 1
    for (int j = 0; ; j++) {
        const int buf = j & 1;
        const unsigned ri = s_ri[buf];        // uniform across block
        if (ri >= N_ROWS) break;

        if (t == 0) s_ri[buf ^ 1] = atomicAdd(&g_tickets[chunk], 1u);  // prefetch

        const int n  = ri / HF;
        const int ty = ri % HF;

        if (active) {
            const float2* base = (const float2*)X
                + (size_t)n * (IMG_H * ROW_F2)
                + (size_t)(ty * 50 + chunk * 10) * ROW_F2
                + t;

            float a[8];
#pragma unroll
            for (int i = 0; i < 8; i++) a[i] = 0.f;

#pragma unroll
            for (int r = 0; r < 10; r++) {
#pragma unroll
                for (int k = 0; k < 4; k++) {
                    const float2 xv = __ldg(base + r * ROW_F2 + k * 400);
                    a[k * 2 + 0] += xv.x * wr[r].x + xv.y * wr[r].y;
                    a[k * 2 + 1] += xv.x * wr[r].z + xv.y * wr[r].w;
                }
            }
#pragma unroll
            for (int k = 0; k < 4; k++) {
                s_part[buf][0][t + k * 400] = a[k * 2 + 0];
                s_part[buf][1][t + k * 400] = a[k * 2 + 1];
            }
        }
        __syncthreads();

        if (t < 128) {
            const int ch = t >> 6, tile = t & 63;
            float s = 0.f;
#pragma unroll
            for (int m = 0; m < 25; m++) s += s_part[buf][ch][tile * 25 + m];
            g_part[chunk][((n * 2 + ch) * HF + ty) * WF + tile] = s;
        }
    }

    // ================= grid barrier =================
    __threadfence();                 // publish this thread's g_part stores
    __syncthreads();                 // all threads' fences done
    if (t == 0) {
        atomicAdd(&g_done, 1u);
        volatile unsigned* d = &g_done;
        while (*d < NBLK) __nanosleep(128);
        __threadfence();             // acquire all blocks' g_part
        // elected-last reset of all counters for the next launch
        if (atomicAdd(&g_done2, 1u) == NBLK - 1u) {
            g_done = 0u;
            g_done2 = 0u;
#pragma unroll
            for (int c = 0; c < 5; c++) g_tickets[c] = 0u;
        }
    }
    __syncthreads();

    // ================= Phase 2: head =================
    if (blockIdx.x >= 112) return;   // 112 blocks x 3 units cover 336 units

    const int sub = t >> 7;          // 0..2 (t<384), unit within block
    const int p   = t & 127;         // position slot within unit
    if (sub >= 3) return;
    const int u   = blockIdx.x * 3 + sub;   // two-row unit 0..335
    const int n   = u / 42;
    const int y0  = (u % 42) * 2;

    // stage feats rows y0-1..y0+2 (zero-padded): sum 5 partials + bias
#pragma unroll
    for (int i = 0; i < 4; i++) {
        const int e  = p + i * 128;          // 0..511
        const int xx = e & 63;
        const int rr = (e >> 6) & 3;
        const int ic = e >> 8;
        const int yy = y0 - 1 + rr;
        float v = 0.0f;
        if (yy >= 0 && yy < HF) {
            const int idx = ((n * 2 + ic) * HF + yy) * WF + xx;
            v = s_cbias[ic];
#pragma unroll
            for (int c = 0; c < 5; c++) v += g_part[c][idx];
        }
        s_f[sub][ic][rr][xx] = v;
    }
    __syncwarp();
    __syncthreads();                 // all subs staged (uniform: t<384 here)

    const int x  = p & 63;
    const int ly = p >> 6;
    const int y  = y0 + ly;

    float f[18];
#pragma unroll
    for (int ic = 0; ic < 2; ic++) {
#pragma unroll
        for (int dy = 0; dy < 3; dy++) {
#pragma unroll
            for (int dx = 0; dx < 3; dx++) {
                const int xx = x + dx - 1;
                float v = 0.0f;
                if (xx >= 0 && xx < WF) v = s_f[sub][ic][ly + dy][xx];
                f[ic * 9 + dy * 3 + dx] = v;
            }
        }
    }

    float c0 = s_cb[0], c1 = s_cb[1];
#pragma unroll
    for (int k = 0; k < 18; k++) {
        c0 += f[k] * s_cw[k];
        c1 += f[k] * s_cw[18 + k];
    }
    const float m  = fmaxf(c0, c1);
    const float e0 = __expf(c0 - m), e1 = __expf(c1 - m);
    const float p1 = e1 / (e0 + e1);
    const float mval = (p1 > 0.95f) ? 1.0f : 0.0f;

    const float gx = ((float)x + 0.5f) * 50.0f;
    const float gy = ((float)y + 0.5f) * 50.0f;
    const float SZ[3] = {16.0f, 32.0f, 64.0f};
    const float RI[3] = {0.70710678118654752f, 1.0f, 1.41421356237309505f};

    float4* pout = out + ((size_t)u * 128 + p) * 9;   // dense 144B per thread
#pragma unroll
    for (int a = 0; a < 9; a++) {
        float o0 = s_bb[a * 4 + 0], o1 = s_bb[a * 4 + 1];
        float o2 = s_bb[a * 4 + 2], o3 = s_bb[a * 4 + 3];
        const float* wp = &s_bw[a * 4 * 18];
#pragma unroll
        for (int kk = 0; kk < 18; kk++) {
            const float fv = f[kk];
            o0 += fv * wp[kk];
            o1 += fv * wp[18 + kk];
            o2 += fv * wp[36 + kk];
            o3 += fv * wp[54 + kk];
        }
        const float s  = SZ[a / 3];
        const float r  = RI[a % 3];
        const float wa = (s / r) * 0.5f;
        const float ha = (s * r) * 0.5f;
        float v0 = fminf(fmaxf(gx - wa + o0, 0.0f), (float)IMG_W);
        float v1 = fminf(fmaxf(gy - ha + o1, 0.0f), (float)IMG_H);
        float v2 = fminf(fmaxf(gx + wa + o2, 0.0f), (float)IMG_W);
        float v3 = fminf(fmaxf(gy + ha + o3, 0.0f), (float)IMG_H);
        pout[a] = make_float4(v0 * mval, v1 * mval, v2 * mval, v3 * mval);
    }
}

extern "C" void kernel_launch(void* const* d_in, const int* in_sizes, int n_in,
                              void* d_out, int out_size)
{
    const float* X      = (const float*)d_in[0];
    const float* conv_w = (const float*)d_in[1];
    const float* conv_b = (const float*)d_in[2];
    const float* box_w  = (const float*)d_in[3];
    const float* box_b  = (const float*)d_in[4];
    const float* cls_w  = (const float*)d_in[5];
    const float* cls_b  = (const float*)d_in[6];
    float4* out = (float4*)d_out;

    // ONE kernel, one graph node. 295 blocks = guaranteed single wave (2/SM).
    rpn_fused_kernel<<<NBLK, 416>>>(X, conv_w, conv_b, box_w, box_b,
                                    cls_w, cls_b, out);
}